// round 6
// baseline (speedup 1.0000x reference)
#include <cuda_runtime.h>

// PCEN, single fused kernel: chunked linear-recurrence scan with smem-cached
// x tiles and a decoupled cross-block checkpoint chain.
//
//   M[t] = a*M[t-1] + s*x[t],  a = 0.975, s = 0.025,  M[0] = x[0]
//   out  = sqrt(x * (M+eps)^(-alpha) + delta) - sqrt(delta)
//
// x: (B=64, T=4000, F=128) fp32. Block = one (b, chunk) pair, 4 warps.
// Phase A: warps scan 20 rows each (zero initial state), staging x in smem.
// Phase B (warp 0): combine warp partials; spin-wait on predecessor chunk's
//   checkpoint; publish this chunk's checkpoint; derive per-warp input states.
// Phase D: warps sweep their rows from smem and write outputs.
// Seed trick: since 1-s == a, pre-state I = x[0] yields M[0] = x[0] exactly,
// so chunk 0 uses I = x[0] (from smem) instead of a predecessor checkpoint.

#define B_LEN   64
#define T_LEN   4000
#define F4      32            // 128 floats = 32 float4 lanes
#define CHUNK   80
#define NCHUNK  50            // T_LEN / CHUNK
#define RPW     20            // rows per warp (CHUNK / 4)
#define NBLK    (B_LEN * NCHUNK)

#define C_S       0.025f
#define C_A       0.975f
#define C_EPS     1e-6f
#define C_NALPHA (-0.98f)
#define C_DELTA   2.0f
#define C_SQRTD   1.41421356237309515f

// a^(20k) propagation factors
#define A20 0.60268800f
#define A40 0.36323283f
#define A60 0.21891607f
#define A80 0.13193809f

// Cross-block chain state: checkpoint M[(c+1)*CHUNK - 1] per (b,c), plus flags.
__device__ float4 g_state[NBLK * F4];   // 1.6 MB
__device__ int    g_flag[NBLK];

__device__ __forceinline__ float f_lg2(float v) {
    float r; asm("lg2.approx.f32 %0, %1;" : "=f"(r) : "f"(v)); return r;
}
__device__ __forceinline__ float f_ex2(float v) {
    float r; asm("ex2.approx.f32 %0, %1;" : "=f"(r) : "f"(v)); return r;
}
__device__ __forceinline__ float f_sqrt(float v) {
    float r; asm("sqrt.approx.f32 %0, %1;" : "=f"(r) : "f"(v)); return r;
}
__device__ __forceinline__ float pcen1(float xv, float mv) {
    return f_sqrt(fmaf(xv, f_ex2(C_NALPHA * f_lg2(mv + C_EPS)), C_DELTA)) - C_SQRTD;
}
__device__ __forceinline__ float4 ema4(float4 m, float4 xv) {
    m.x = fmaf(C_A, m.x, C_S * xv.x);
    m.y = fmaf(C_A, m.y, C_S * xv.y);
    m.z = fmaf(C_A, m.z, C_S * xv.z);
    m.w = fmaf(C_A, m.w, C_S * xv.w);
    return m;
}
__device__ __forceinline__ float4 comb4(float aL, float4 I, float4 P) {
    float4 r;
    r.x = fmaf(aL, I.x, P.x);
    r.y = fmaf(aL, I.y, P.y);
    r.z = fmaf(aL, I.z, P.z);
    r.w = fmaf(aL, I.w, P.w);
    return r;
}

__global__ void pcen_init_flags() {
    int i = blockIdx.x * blockDim.x + threadIdx.x;
    if (i < NBLK) g_flag[i] = 0;
}

__global__ void __launch_bounds__(128)
pcen_fused(const float4* __restrict__ x4, float4* __restrict__ out4) {
    __shared__ float4 tile[CHUNK * F4];     // 40960 B: the x chunk
    __shared__ float4 part[4][F4];          // zero-state warp partials
    __shared__ float4 warp_in[4][F4];       // resolved per-warp input states

    const int bid = blockIdx.x;
    const int b   = bid / NCHUNK;
    const int c   = bid - b * NCHUNK;
    const int w   = threadIdx.x >> 5;
    const int l   = threadIdx.x & 31;

    const size_t gbase = ((size_t)(b * T_LEN + c * CHUNK + w * RPW)) * F4 + l;
    const float4* px = x4 + gbase;

    // ---- Phase A: stage x in smem + zero-state partial EMA per warp ----
    float4 m = make_float4(0.f, 0.f, 0.f, 0.f);
    #pragma unroll 4
    for (int i = 0; i < RPW; ++i) {
        const float4 xv = px[(size_t)i * F4];
        tile[(w * RPW + i) * F4 + l] = xv;
        m = ema4(m, xv);
    }
    part[w][l] = m;
    __syncthreads();

    // ---- Phase B/C: warp 0 resolves the chain ----
    if (w == 0) {
        const float4 m0 = part[0][l];
        const float4 m1 = part[1][l];
        const float4 m2 = part[2][l];
        const float4 m3 = part[3][l];
        // zero-state prefixes across warps
        const float4 P0 = m0;
        const float4 P1 = comb4(A20, P0, m1);
        const float4 P2 = comb4(A20, P1, m2);
        const float4 P3 = comb4(A20, P2, m3);

        float4 I;
        if (c > 0) {
            volatile int* f = &g_flag[bid - 1];
            while (*f == 0) { }
            __threadfence();
            I = g_state[(size_t)(bid - 1) * F4 + l];
        } else {
            I = tile[l];   // pre-state x[0]: a*x0 + s*x0 == x0
        }

        if (c < NCHUNK - 1) {
            g_state[(size_t)bid * F4 + l] = comb4(A80, I, P3);
            __threadfence();
            __syncwarp();
            if (l == 0) *((volatile int*)&g_flag[bid]) = 1;
        }

        warp_in[0][l] = I;
        warp_in[1][l] = comb4(A20, I, P0);
        warp_in[2][l] = comb4(A40, I, P1);
        warp_in[3][l] = comb4(A60, I, P2);
    }
    __syncthreads();

    // ---- Phase D: output sweep from smem ----
    float4* po = out4 + gbase;
    m = warp_in[w][l];
    #pragma unroll 4
    for (int i = 0; i < RPW; ++i) {
        const float4 xv = tile[(w * RPW + i) * F4 + l];
        m = ema4(m, xv);
        float4 o;
        o.x = pcen1(xv.x, m.x);
        o.y = pcen1(xv.y, m.y);
        o.z = pcen1(xv.z, m.z);
        o.w = pcen1(xv.w, m.w);
        po[(size_t)i * F4] = o;
    }
}

extern "C" void kernel_launch(void* const* d_in, const int* in_sizes, int n_in,
                              void* d_out, int out_size) {
    const float4* x4 = (const float4*)d_in[0];
    float4* out4 = (float4*)d_out;
    (void)in_sizes; (void)n_in; (void)out_size;

    pcen_init_flags<<<(NBLK + 255) / 256, 256>>>();
    pcen_fused<<<NBLK, 128>>>(x4, out4);
}

// round 7
// speedup vs baseline: 1.1131x; 1.1131x over previous
#include <cuda_runtime.h>

// PCEN via exact linear-recurrence chunk decomposition, batch-group pipelined
// for L2 reuse of x between the partial pass and the output pass.
//
//   M[t] = a*M[t-1] + s*x[t],  a = 0.975, s = 0.025,  M[0] = x[0]
//   out  = sqrt(x * (M+eps)^(-alpha) + delta) - sqrt(delta)
//
// x: (B=64, T=4000, F=128) fp32. Per batch group g (16 batches = 33 MB):
//   P1(g): per-(b,chunk) warp computes zero-state local EMA  (reads x: DRAM)
//   C(g):  serial combine of 80 chunk partials per (b,f) chain (tiny)
//   P3(g): per-(b,chunk) warp resumes from exact checkpoint, writes output
//          (re-reads x: mostly L2 hits; out written with streaming hint)
// a^50 ~= 0.282, so cross-chunk rounding decays geometrically (rel_err ~2e-7).

#define B_LEN   64
#define T_LEN   4000
#define F4      32            // 128 floats = 32 float4 lanes
#define CHUNK   50
#define NCHUNK  80            // T_LEN / CHUNK
#define GB      16            // batches per group
#define NGROUP  (B_LEN / GB)  // 4

#define C_S       0.025f
#define C_A       0.975f
#define C_EPS     1e-6f
#define C_NALPHA (-0.98f)
#define C_DELTA   2.0f
#define C_SQRTD   1.41421356237309515f

// Scratch: chunk-local zero-state partials and resolved checkpoints.
__device__ float4 g_local[B_LEN * NCHUNK * F4];        // 2.6 MB
__device__ float4 g_ckpt [B_LEN * (NCHUNK - 1) * F4];  // 2.6 MB

__device__ __forceinline__ float f_lg2(float v) {
    float r; asm("lg2.approx.f32 %0, %1;" : "=f"(r) : "f"(v)); return r;
}
__device__ __forceinline__ float f_ex2(float v) {
    float r; asm("ex2.approx.f32 %0, %1;" : "=f"(r) : "f"(v)); return r;
}
__device__ __forceinline__ float f_sqrt(float v) {
    float r; asm("sqrt.approx.f32 %0, %1;" : "=f"(r) : "f"(v)); return r;
}
__device__ __forceinline__ float pcen1(float xv, float mv) {
    return f_sqrt(fmaf(xv, f_ex2(C_NALPHA * f_lg2(mv + C_EPS)), C_DELTA)) - C_SQRTD;
}
__device__ __forceinline__ float4 ema4(float4 m, float4 xv) {
    m.x = fmaf(C_A, m.x, C_S * xv.x);
    m.y = fmaf(C_A, m.y, C_S * xv.y);
    m.z = fmaf(C_A, m.z, C_S * xv.z);
    m.w = fmaf(C_A, m.w, C_S * xv.w);
    return m;
}
__device__ __forceinline__ float4 comb4(float aL, float4 I, float4 P) {
    float4 r;
    r.x = fmaf(aL, I.x, P.x);
    r.y = fmaf(aL, I.y, P.y);
    r.z = fmaf(aL, I.z, P.z);
    r.w = fmaf(aL, I.w, P.w);
    return r;
}

// ---- P1: chunk-local EMA partials for one batch group ----
// grid: GB*NCHUNK/4 blocks x 128; warp = one (b, c) pair.
__global__ void __launch_bounds__(128)
pcen_local(const float4* __restrict__ x4, int b0) {
    const int p    = blockIdx.x * 4 + (threadIdx.x >> 5);   // b_local*NCHUNK + c
    const int lane = threadIdx.x & 31;
    const int c    = p % NCHUNK;
    const int b    = b0 + p / NCHUNK;

    const float4* px = x4 + (size_t)(b * T_LEN + c * CHUNK) * F4 + lane;

    float4 m;
    int i0;
    if (c == 0) {            // real initial state: M[0] = x[0]
        m = px[0];
        i0 = 1;
    } else {                 // zero-state local partial
        m = make_float4(0.f, 0.f, 0.f, 0.f);
        i0 = 0;
    }

    #pragma unroll 10
    for (int i = i0; i < CHUNK; ++i) {
        m = ema4(m, px[(size_t)i * F4]);
    }
    g_local[(size_t)(b * NCHUNK + c) * F4 + lane] = m;
}

// ---- C: serial combine across chunks for one batch group (tiny) ----
// GB*32 = 512 threads; each owns one (b, f4-lane) chain, NCHUNK-1 FMAs.
__global__ void __launch_bounds__(256)
pcen_combine(int b0) {
    const int tid  = blockIdx.x * blockDim.x + threadIdx.x;
    if (tid >= GB * F4) return;
    const int b    = b0 + (tid >> 5);
    const int lane = tid & 31;

    // a^CHUNK in double for accuracy (cost irrelevant here).
    double ad = 1.0;
    for (int i = 0; i < CHUNK; ++i) ad *= 0.975;
    const float aL = (float)ad;

    float4 m = g_local[(size_t)(b * NCHUNK + 0) * F4 + lane];   // true M[CHUNK-1]
    g_ckpt[(size_t)(b * (NCHUNK - 1) + 0) * F4 + lane] = m;     // ckpt for chunk 1
    #pragma unroll 8
    for (int k = 1; k < NCHUNK - 1; ++k) {
        const float4 lk = g_local[(size_t)(b * NCHUNK + k) * F4 + lane];
        m = comb4(aL, m, lk);
        g_ckpt[(size_t)(b * (NCHUNK - 1) + k) * F4 + lane] = m; // ckpt for chunk k+1
    }
}

// ---- P3: output sweep per chunk for one batch group ----
// Same (b, c)-per-warp mapping as P1; x re-read should hit L2.
__global__ void __launch_bounds__(128)
pcen_out(const float4* __restrict__ x4, float4* __restrict__ out4, int b0) {
    const int p    = blockIdx.x * 4 + (threadIdx.x >> 5);
    const int lane = threadIdx.x & 31;
    const int c    = p % NCHUNK;
    const int b    = b0 + p / NCHUNK;

    const size_t base = (size_t)(b * T_LEN + c * CHUNK) * F4 + lane;
    const float4* px = x4 + base;
    float4*       po = out4 + base;

    float4 m;
    if (c == 0) {
        // Pre-state x[0]: a*x0 + s*x0 == x0, so the uniform update is exact.
        m = px[0];
    } else {
        m = g_ckpt[(size_t)(b * (NCHUNK - 1) + (c - 1)) * F4 + lane];
    }

    #pragma unroll 5
    for (int i = 0; i < CHUNK; ++i) {
        const float4 xv = px[(size_t)i * F4];
        m = ema4(m, xv);
        float4 o;
        o.x = pcen1(xv.x, m.x);
        o.y = pcen1(xv.y, m.y);
        o.z = pcen1(xv.z, m.z);
        o.w = pcen1(xv.w, m.w);
        __stcs(&po[(size_t)i * F4], o);   // streaming store: don't pollute L2
    }
}

extern "C" void kernel_launch(void* const* d_in, const int* in_sizes, int n_in,
                              void* d_out, int out_size) {
    const float4* x4 = (const float4*)d_in[0];
    float4* out4 = (float4*)d_out;
    (void)in_sizes; (void)n_in; (void)out_size;

    const int blocks = GB * NCHUNK / 4;   // 320 blocks per pass per group
    for (int g = 0; g < NGROUP; ++g) {
        const int b0 = g * GB;
        pcen_local  <<<blocks, 128>>>(x4, b0);
        pcen_combine<<<2, 256>>>(b0);
        pcen_out    <<<blocks, 128>>>(x4, out4, b0);
    }
}

// round 10
// speedup vs baseline: 2.3373x; 2.0998x over previous
#include <cuda_runtime.h>

// PCEN via exact linear-recurrence chunk decomposition (3 full-width passes).
//
//   M[t] = a*M[t-1] + s*x[t],  a = 0.975, s = 0.025,  M[0] = x[0]
//   out  = sqrt(x * (M+eps)^(-alpha) + delta) - sqrt(delta)
//
// x: (B=64, T=4000, F=128) fp32.
//   P1: per-(b,chunk) warp computes zero-state local EMA over its 50 rows.
//       1280 blocks -> ~35 warps/SM for max MLP.
//   C : 2048 threads, serial combine of 80 partials per (b,f4) chain (tiny).
//   P3: per-(b,chunk) warp resumes from exact checkpoint, writes output
//       with streaming stores.
// a^50 ~= 0.282: cross-chunk rounding decays geometrically (rel_err ~2e-7).

#define B_LEN   64
#define T_LEN   4000
#define F4      32            // 128 floats = 32 float4 lanes
#define CHUNK   50
#define NCHUNK  80            // T_LEN / CHUNK
#define NPAIR   (B_LEN * NCHUNK)   // 5120 (b,c) pairs

#define C_S       0.025f
#define C_A       0.975f
#define C_EPS     1e-6f
#define C_NALPHA (-0.98f)
#define C_DELTA   2.0f
#define C_SQRTD   1.41421356237309515f

// Scratch: chunk-local zero-state partials and resolved checkpoints.
__device__ float4 g_local[B_LEN * NCHUNK * F4];        // 2.6 MB
__device__ float4 g_ckpt [B_LEN * (NCHUNK - 1) * F4];  // 2.6 MB

__device__ __forceinline__ float f_lg2(float v) {
    float r; asm("lg2.approx.f32 %0, %1;" : "=f"(r) : "f"(v)); return r;
}
__device__ __forceinline__ float f_ex2(float v) {
    float r; asm("ex2.approx.f32 %0, %1;" : "=f"(r) : "f"(v)); return r;
}
__device__ __forceinline__ float f_sqrt(float v) {
    float r; asm("sqrt.approx.f32 %0, %1;" : "=f"(r) : "f"(v)); return r;
}
__device__ __forceinline__ float pcen1(float xv, float mv) {
    return f_sqrt(fmaf(xv, f_ex2(C_NALPHA * f_lg2(mv + C_EPS)), C_DELTA)) - C_SQRTD;
}
__device__ __forceinline__ float4 ema4(float4 m, float4 xv) {
    m.x = fmaf(C_A, m.x, C_S * xv.x);
    m.y = fmaf(C_A, m.y, C_S * xv.y);
    m.z = fmaf(C_A, m.z, C_S * xv.z);
    m.w = fmaf(C_A, m.w, C_S * xv.w);
    return m;
}
__device__ __forceinline__ float4 comb4(float aL, float4 I, float4 P) {
    float4 r;
    r.x = fmaf(aL, I.x, P.x);
    r.y = fmaf(aL, I.y, P.y);
    r.z = fmaf(aL, I.z, P.z);
    r.w = fmaf(aL, I.w, P.w);
    return r;
}

// ---- P1: chunk-local EMA partials, full batch set ----
// grid: NPAIR/4 = 1280 blocks x 128 threads; warp = one (b, c) pair.
__global__ void __launch_bounds__(128)
pcen_local(const float4* __restrict__ x4) {
    const int p    = blockIdx.x * 4 + (threadIdx.x >> 5);   // b*NCHUNK + c
    const int lane = threadIdx.x & 31;
    const int c    = p % NCHUNK;
    const int b    = p / NCHUNK;

    const float4* px = x4 + (size_t)(b * T_LEN + c * CHUNK) * F4 + lane;

    float4 m;
    int i0;
    if (c == 0) {            // real initial state: M[0] = x[0]
        m = px[0];
        i0 = 1;
    } else {                 // zero-state local partial
        m = make_float4(0.f, 0.f, 0.f, 0.f);
        i0 = 0;
    }

    #pragma unroll 10
    for (int i = i0; i < CHUNK; ++i) {
        m = ema4(m, px[(size_t)i * F4]);
    }
    g_local[(size_t)p * F4 + lane] = m;
}

// ---- C: serial combine across all 80 chunks per (b, f4-lane) chain ----
// B_LEN*F4 = 2048 threads; 79 FMAs each.
__global__ void __launch_bounds__(256)
pcen_combine() {
    const int tid  = blockIdx.x * blockDim.x + threadIdx.x;
    if (tid >= B_LEN * F4) return;
    const int b    = tid >> 5;
    const int lane = tid & 31;

    // a^CHUNK in double for accuracy (cost irrelevant here).
    double ad = 1.0;
    for (int i = 0; i < CHUNK; ++i) ad *= 0.975;
    const float aL = (float)ad;

    float4 m = g_local[(size_t)(b * NCHUNK + 0) * F4 + lane];   // true M[CHUNK-1]
    g_ckpt[(size_t)(b * (NCHUNK - 1) + 0) * F4 + lane] = m;     // ckpt for chunk 1
    #pragma unroll 8
    for (int k = 1; k < NCHUNK - 1; ++k) {
        const float4 lk = g_local[(size_t)(b * NCHUNK + k) * F4 + lane];
        m = comb4(aL, m, lk);
        g_ckpt[(size_t)(b * (NCHUNK - 1) + k) * F4 + lane] = m; // ckpt for chunk k+1
    }
}

// ---- P3: output sweep per chunk, full batch set ----
// Same (b, c)-per-warp mapping as P1.
__global__ void __launch_bounds__(128)
pcen_out(const float4* __restrict__ x4, float4* __restrict__ out4) {
    const int p    = blockIdx.x * 4 + (threadIdx.x >> 5);
    const int lane = threadIdx.x & 31;
    const int c    = p % NCHUNK;
    const int b    = p / NCHUNK;

    const size_t base = (size_t)(b * T_LEN + c * CHUNK) * F4 + lane;
    const float4* px = x4 + base;
    float4*       po = out4 + base;

    float4 m;
    if (c == 0) {
        // Pre-state x[0]: a*x0 + s*x0 == x0, so the uniform update is exact.
        m = px[0];
    } else {
        m = g_ckpt[(size_t)(b * (NCHUNK - 1) + (c - 1)) * F4 + lane];
    }

    #pragma unroll 5
    for (int i = 0; i < CHUNK; ++i) {
        const float4 xv = px[(size_t)i * F4];
        m = ema4(m, xv);
        float4 o;
        o.x = pcen1(xv.x, m.x);
        o.y = pcen1(xv.y, m.y);
        o.z = pcen1(xv.z, m.z);
        o.w = pcen1(xv.w, m.w);
        __stcs(&po[(size_t)i * F4], o);   // streaming store: keep L2 clean
    }
}

extern "C" void kernel_launch(void* const* d_in, const int* in_sizes, int n_in,
                              void* d_out, int out_size) {
    const float4* x4 = (const float4*)d_in[0];
    float4* out4 = (float4*)d_out;
    (void)in_sizes; (void)n_in; (void)out_size;

    pcen_local  <<<NPAIR / 4, 128>>>(x4);
    pcen_combine<<<(B_LEN * F4 + 255) / 256, 256>>>();
    pcen_out    <<<NPAIR / 4, 128>>>(x4, out4);
}